// round 17
// baseline (speedup 1.0000x reference)
#include <cuda_runtime.h>
#include <math.h>

#define HH 240
#define WW 320
#define HWP (HH*WW)
#define BB 4
#define CIN 64
#define COUT 24
#define HS 120
#define WS 160
#define NUMK 8
#define QW 9600   /* HWP/8 */

// ---- scratch (static device globals: allowed; no allocation) ----
__device__ float  g_oa[BB*COUT*HWP];     // conv output (only ch 16..23 aff_raw consumed by fused)
__device__ float2 g_off2[BB*NUMK*HWP];   // packed offsets: [b][k][P] = (dy, dx)
__device__ float  g_feahwc[BB*HWP*8];    // upsampled features HWC
__device__ float  g_U[CIN*16*25];        // Winograd weights, PRE-PADDED stride-25 rows

__device__ __forceinline__ float tanh_fast(float x) {
    float y;
    asm("tanh.approx.f32 %0, %1;" : "=f"(y) : "f"(x));
    return y;
}

// ============================================================================
// bilinear with zeros padding (matches reference _bilinear_zeros) — conf path
// ============================================================================
__device__ __forceinline__ float bilin0(const float* __restrict__ img, float x, float y,
                                        int Hi, int Wi) {
    float xf = floorf(x), yf = floorf(y);
    float wx = x - xf, wy = y - yf;
    int x0 = (int)xf, y0 = (int)yf;
    int x1 = x0 + 1, y1 = y0 + 1;

    bool xv0 = (x0 >= 0) && (x0 <= Wi - 1);
    bool xv1 = (x1 >= 0) && (x1 <= Wi - 1);
    bool yv0 = (y0 >= 0) && (y0 <= Hi - 1);
    bool yv1 = (y1 >= 0) && (y1 <= Hi - 1);

    int xc0 = min(max(x0, 0), Wi - 1);
    int xc1 = min(max(x1, 0), Wi - 1);
    int yc0 = min(max(y0, 0), Hi - 1);
    int yc1 = min(max(y1, 0), Hi - 1);

    float v00 = (xv0 && yv0) ? img[yc0 * Wi + xc0] : 0.0f;
    float v10 = (xv1 && yv0) ? img[yc0 * Wi + xc1] : 0.0f;
    float v01 = (xv0 && yv1) ? img[yc1 * Wi + xc0] : 0.0f;
    float v11 = (xv1 && yv1) ? img[yc1 * Wi + xc1] : 0.0f;

    return v00 * ((1.0f - wy) * (1.0f - wx))
         + v10 * ((1.0f - wy) * wx)
         + v01 * (wy * (1.0f - wx))
         + v11 * (wy * wx);
}

// ============================================================================
// Kernel 1: 2x bilinear upsample (HWC only) + zero ch 8/9 of offset_full.
// ============================================================================
__global__ void upsample_kernel(const float* __restrict__ tgt, float* __restrict__ out) {
    int idx = blockIdx.x * blockDim.x + threadIdx.x;
    if (idx >= BB * HWP) return;
    int b = idx / HWP;
    int P = idx - b * HWP;
    int y = P / WW, x = P - (P / WW) * WW;

    out[((size_t)b * 18 + 8) * HWP + P] = 0.0f;
    out[((size_t)b * 18 + 9) * HWP + P] = 0.0f;

    int ty = y >> 1, tx = x >> 1;
    int y0, y1, x0, x1;
    float wy0, wy1, wx0, wx1;
    if (y & 1) { y0 = ty; y1 = min(ty + 1, HS - 1); wy0 = 0.75f; wy1 = 0.25f; }
    else       { y0 = max(ty - 1, 0); y1 = ty;      wy0 = 0.25f; wy1 = 0.75f; }
    if (x & 1) { x0 = tx; x1 = min(tx + 1, WS - 1); wx0 = 0.75f; wx1 = 0.25f; }
    else       { x0 = max(tx - 1, 0); x1 = tx;      wx0 = 0.25f; wx1 = 0.75f; }

    const float* base = tgt + b * 8 * HS * WS;
    float vv[8];
    #pragma unroll
    for (int c = 0; c < 8; c++) {
        const float* pl = base + c * HS * WS;
        float r0 = wx0 * pl[y0 * WS + x0] + wx1 * pl[y0 * WS + x1];
        float r1 = wx0 * pl[y1 * WS + x0] + wx1 * pl[y1 * WS + x1];
        vv[c] = wy0 * r0 + wy1 * r1;
    }
    float4* dst = (float4*)(g_feahwc + ((size_t)b * HWP + P) * 8);
    dst[0] = make_float4(vv[0], vv[1], vv[2], vv[3]);
    dst[1] = make_float4(vv[4], vv[5], vv[6], vv[7]);
}

// ============================================================================
// Kernel 2: Winograd F(2,3) weight transform (pre-padded stride-25 rows)
// ============================================================================
__global__ void wino_weights_kernel(const float* __restrict__ wgt) {
    int t = blockIdx.x * blockDim.x + threadIdx.x;
    if (t >= CIN * COUT) return;
    int ci = t / COUT;
    int co = t - ci * COUT;

    float g[9];
    #pragma unroll
    for (int r = 0; r < 9; r++) g[r] = __ldg(wgt + ((size_t)co * CIN + ci) * 9 + r);

    float q[4][3];
    #pragma unroll
    for (int c = 0; c < 3; c++) {
        float g0 = g[c], g1 = g[3 + c], g2 = g[6 + c];
        q[0][c] = g0;
        q[1][c] = 0.5f * (g0 + g1 + g2);
        q[2][c] = 0.5f * (g0 - g1 + g2);
        q[3][c] = g2;
    }
    #pragma unroll
    for (int i = 0; i < 4; i++) {
        float v0 = q[i][0], v1 = q[i][1], v2 = q[i][2];
        g_U[(ci * 16 + i * 4 + 0) * 25 + co] = v0;
        g_U[(ci * 16 + i * 4 + 1) * 25 + co] = 0.5f * (v0 + v1 + v2);
        g_U[(ci * 16 + i * 4 + 2) * 25 + co] = 0.5f * (v0 - v1 + v2);
        g_U[(ci * 16 + i * 4 + 3) * 25 + co] = v2;
    }
}

// ============================================================================
// Kernel 3: Winograd F(2x2,3x3) conv 64->24 + bias (unchanged from best).
// ============================================================================
#define SV_ELEMS (8*16*36)
#define SM_ELEMS (32*12*18)
#define USLAB    (8*16*25)
#define WINO_SMEM ((SV_ELEMS + SM_ELEMS) * 4)

__global__ __launch_bounds__(256, 2) void conv_wino_kernel(
    const float* __restrict__ gin, const float* __restrict__ bias,
    float* __restrict__ out) {
    extern __shared__ float smem[];
    float* sV = smem;
    float* sM = smem + SV_ELEMS;
    float* sU = smem + SV_ELEMS;

    int tid = threadIdx.x;
    int p  = tid & 15;
    int cg = (tid >> 4) & 3;
    int tq = tid >> 6;
    int bx = blockIdx.x, by = blockIdx.y, b = blockIdx.z;

    float acc[8][6];
    #pragma unroll
    for (int i = 0; i < 8; i++)
        #pragma unroll
        for (int c = 0; c < 6; c++) acc[i][c] = 0.0f;

    const float* gb = gin + (size_t)b * CIN * HWP;

    int ttile = tid & 31;
    int tciq  = tid >> 5;
    int ttx = ttile & 7, tty = ttile >> 3;
    int tgx0 = bx * 16 + ttx * 2 - 1;
    int tgy0 = by * 8 + tty * 2 - 1;
    bool xin = (tgx0 >= 0 && tgx0 + 3 < WW);

    int ro[4];
    bool rok[4];
    bool cok[4];
    #pragma unroll
    for (int rr = 0; rr < 4; rr++) {
        int yy = tgy0 + rr;
        rok[rr] = (yy >= 0 && yy < HH);
        ro[rr] = yy * WW + tgx0;
    }
    #pragma unroll
    for (int c = 0; c < 4; c++) {
        int xx = tgx0 + c;
        cok[c] = (xx >= 0 && xx < WW);
    }

    bool utail = (tid < USLAB - 12 * 256);

    float r[4][4];
    float ureg[13];
    {
        const float* pl = gb + (size_t)tciq * HWP;
        #pragma unroll
        for (int rr = 0; rr < 4; rr++) {
            if (rok[rr]) {
                if (xin) {
                    r[rr][0] = __ldg(pl + ro[rr]);
                    r[rr][1] = __ldg(pl + ro[rr] + 1);
                    r[rr][2] = __ldg(pl + ro[rr] + 2);
                    r[rr][3] = __ldg(pl + ro[rr] + 3);
                } else {
                    #pragma unroll
                    for (int c = 0; c < 4; c++)
                        r[rr][c] = cok[c] ? __ldg(pl + ro[rr] + c) : 0.0f;
                }
            } else {
                r[rr][0] = r[rr][1] = r[rr][2] = r[rr][3] = 0.0f;
            }
        }
        const float* us = g_U;
        #pragma unroll
        for (int k = 0; k < 12; k++) ureg[k] = __ldg(us + tid + k * 256);
        ureg[12] = utail ? __ldg(us + tid + 12 * 256) : 0.0f;
    }

    for (int g8 = 0; g8 < 8; g8++) {
        float e0[4], e1[4], e2[4], e3[4];
        #pragma unroll
        for (int c = 0; c < 4; c++) {
            e0[c] = r[0][c] - r[2][c];
            e1[c] = r[1][c] + r[2][c];
            e2[c] = r[2][c] - r[1][c];
            e3[c] = r[1][c] - r[3][c];
        }

        __syncthreads();

        {
            float* svb = sV + tciq * 16 * 36 + ttile;
            #pragma unroll
            for (int i = 0; i < 4; i++) {
                const float* er = (i == 0) ? e0 : (i == 1) ? e1 : (i == 2) ? e2 : e3;
                svb[(i * 4 + 0) * 36] = er[0] - er[2];
                svb[(i * 4 + 1) * 36] = er[1] + er[2];
                svb[(i * 4 + 2) * 36] = er[2] - er[1];
                svb[(i * 4 + 3) * 36] = er[1] - er[3];
            }
            #pragma unroll
            for (int k = 0; k < 12; k++) sU[tid + k * 256] = ureg[k];
            if (utail) sU[tid + 12 * 256] = ureg[12];
        }
        __syncthreads();

        if (g8 < 7) {
            const float* pl = gb + (size_t)((g8 + 1) * 8 + tciq) * HWP;
            #pragma unroll
            for (int rr = 0; rr < 4; rr++) {
                if (rok[rr]) {
                    if (xin) {
                        r[rr][0] = __ldg(pl + ro[rr]);
                        r[rr][1] = __ldg(pl + ro[rr] + 1);
                        r[rr][2] = __ldg(pl + ro[rr] + 2);
                        r[rr][3] = __ldg(pl + ro[rr] + 3);
                    } else {
                        #pragma unroll
                        for (int c = 0; c < 4; c++)
                            r[rr][c] = cok[c] ? __ldg(pl + ro[rr] + c) : 0.0f;
                    }
                } else {
                    r[rr][0] = r[rr][1] = r[rr][2] = r[rr][3] = 0.0f;
                }
            }
            const float* us = g_U + (g8 + 1) * USLAB;
            #pragma unroll
            for (int k = 0; k < 12; k++) ureg[k] = __ldg(us + tid + k * 256);
            ureg[12] = utail ? __ldg(us + tid + 12 * 256) : 0.0f;
        }

        #pragma unroll
        for (int ciq = 0; ciq < 8; ciq++) {
            const float* vb = sV + (ciq * 16 + p) * 36 + tq * 8;
            float4 va = *(const float4*)(vb);
            float4 vb4 = *(const float4*)(vb + 4);
            float Vv[8] = {va.x, va.y, va.z, va.w, vb4.x, vb4.y, vb4.z, vb4.w};
            const float* Up = sU + (ciq * 16 + p) * 25 + cg * 6;
            float Uu[6];
            #pragma unroll
            for (int c = 0; c < 6; c++) Uu[c] = Up[c];
            #pragma unroll
            for (int c = 0; c < 6; c++)
                #pragma unroll
                for (int i = 0; i < 8; i++)
                    acc[i][c] = fmaf(Vv[i], Uu[c], acc[i][c]);
        }
    }

    #pragma unroll
    for (int pp = 0; pp < 2; pp++) {
        __syncthreads();
        if ((cg >> 1) == pp) {
            #pragma unroll
            for (int i = 0; i < 8; i++)
                #pragma unroll
                for (int c = 0; c < 6; c++)
                    sM[((tq * 8 + i) * 12 + (cg & 1) * 6 + c) * 18 + p] = acc[i][c];
        }
        __syncthreads();

        if (tid < 192) {
            int tile = tid & 31;
            int cop = tid >> 5;
            int tx = tile & 7, ty = tile >> 3;
            int gx = bx * 16 + tx * 2;
            int gy = by * 8 + ty * 2;
            int pix = gy * WW + gx;

            float y2[2][2][2];
            #pragma unroll
            for (int s = 0; s < 2; s++) {
                int col = cop * 2 + s;
                int co = pp * 12 + col;
                float m[16];
                #pragma unroll
                for (int q = 0; q < 16; q++) m[q] = sM[(tile * 12 + col) * 18 + q];
                float r0[4], r1[4];
                #pragma unroll
                for (int j = 0; j < 4; j++) {
                    r0[j] = m[j] + m[4 + j] + m[8 + j];
                    r1[j] = m[4 + j] - m[8 + j] - m[12 + j];
                }
                float bv = __ldg(bias + co);
                y2[s][0][0] = r0[0] + r0[1] + r0[2] + bv;
                y2[s][0][1] = r0[1] - r0[2] - r0[3] + bv;
                y2[s][1][0] = r1[0] + r1[1] + r1[2] + bv;
                y2[s][1][1] = r1[1] - r1[2] - r1[3] + bv;

                if (co >= 16) {
                    float* oa = g_oa + ((size_t)b * COUT + co) * HWP + pix;
                    oa[0] = y2[s][0][0]; oa[1] = y2[s][0][1];
                    oa[WW] = y2[s][1][0]; oa[WW + 1] = y2[s][1][1];
                } else {
                    int oc = (co < 8) ? co : co + 2;
                    float* o = out + ((size_t)b * 18 + oc) * HWP + pix;
                    o[0] = y2[s][0][0]; o[1] = y2[s][0][1];
                    o[WW] = y2[s][1][0]; o[WW + 1] = y2[s][1][1];
                }
            }
            int co0g = pp * 12 + cop * 2;
            if (co0g < 16) {
                float2* op = g_off2 + ((size_t)b * NUMK + (co0g >> 1)) * HWP + pix;
                op[0]      = make_float2(y2[0][0][0], y2[1][0][0]);
                op[1]      = make_float2(y2[0][0][1], y2[1][0][1]);
                op[WW]     = make_float2(y2[0][1][0], y2[1][1][0]);
                op[WW + 1] = make_float2(y2[0][1][1], y2[1][1][1]);
            }
        }
    }
}

// ============================================================================
// Kernel 4: fused cos-affinity + confidence + TGASS + softmax (donor form).
// One thread per donor P2; bilinear weights computed once per (P2,k); all 8
// channels fetched per tap as 2x LDG.128 from HWC. S -> smem row stride 65
// (65*8 = 8 mod 32: the 4 donor-groups/warp land on disjoint bank octets ->
// conflict-free phase-2 reads; phase-1 writes are SCALAR STS.32 because a
// 65-float row base is NOT 16B-aligned — the R15 float4 store trapped).
// Phase 2: lane l owns pixel P = 9600*l + q; epilogue fully thread-local.
// smem: 256*65*4 = 66560 B -> 3 CTAs/SM.
// ============================================================================
#define FUSED_SMEM (256*65*4)

__global__ __launch_bounds__(256) void fused_kernel(const float* __restrict__ gtconf,
                                                    const float* __restrict__ ascp,
                                                    float* __restrict__ out) {
    extern __shared__ float sS[];    // [donor 256][65] : [k*8 + c]
    int tid = threadIdx.x;
    int g0 = blockIdx.x * 256;
    int b = g0 / HWP;
    int p20 = g0 - b * HWP;
    int P2 = p20 + tid;
    int i2 = P2 / WW, j2 = P2 - i2 * WW;

    const float2* off_b = g_off2 + (size_t)b * NUMK * HWP;
    const float*  hwc   = g_feahwc + (size_t)b * HWP * 8;

    // ---- phase 1: sample all 8 channels at coords(P2, k), weights once ----
    #pragma unroll
    for (int k = 0; k < 8; k++) {
        float2 o = off_b[(size_t)k * HWP + P2];
        float base = (k < 4) ? (float)i2 : (float)j2;   // faithful to ref's repeat bug
        float x = o.x + base, y = o.y + base;
        float xf = floorf(x), yf = floorf(y);
        float wx = x - xf, wy = y - yf;
        int x0 = (int)xf, y0 = (int)yf;
        int x1 = x0 + 1, y1 = y0 + 1;
        bool xv0 = (x0 >= 0) && (x0 < WW), xv1 = (x1 >= 0) && (x1 < WW);
        bool yv0 = (y0 >= 0) && (y0 < HH), yv1 = (y1 >= 0) && (y1 < HH);
        int xc0 = min(max(x0, 0), WW - 1), xc1 = min(max(x1, 0), WW - 1);
        int yc0 = min(max(y0, 0), HH - 1), yc1 = min(max(y1, 0), HH - 1);
        float w00 = (1.0f - wy) * (1.0f - wx) * (float)(xv0 && yv0);
        float w10 = (1.0f - wy) * wx          * (float)(xv1 && yv0);
        float w01 = wy * (1.0f - wx)          * (float)(xv0 && yv1);
        float w11 = wy * wx                   * (float)(xv1 && yv1);

        const float4* t00 = (const float4*)(hwc + (size_t)(yc0 * WW + xc0) * 8);
        const float4* t10 = (const float4*)(hwc + (size_t)(yc0 * WW + xc1) * 8);
        const float4* t01 = (const float4*)(hwc + (size_t)(yc1 * WW + xc0) * 8);
        const float4* t11 = (const float4*)(hwc + (size_t)(yc1 * WW + xc1) * 8);
        float4 a0 = t00[0], a1 = t00[1];
        float4 b0 = t10[0], b1 = t10[1];
        float4 c0 = t01[0], c1 = t01[1];
        float4 d0 = t11[0], d1 = t11[1];

        float* dst = sS + tid * 65 + k * 8;
        dst[0] = w00*a0.x + w10*b0.x + w01*c0.x + w11*d0.x;
        dst[1] = w00*a0.y + w10*b0.y + w01*c0.y + w11*d0.y;
        dst[2] = w00*a0.z + w10*b0.z + w01*c0.z + w11*d0.z;
        dst[3] = w00*a0.w + w10*b0.w + w01*c0.w + w11*d0.w;
        dst[4] = w00*a1.x + w10*b1.x + w01*c1.x + w11*d1.x;
        dst[5] = w00*a1.y + w10*b1.y + w01*c1.y + w11*d1.y;
        dst[6] = w00*a1.z + w10*b1.z + w01*c1.z + w11*d1.z;
        dst[7] = w00*a1.w + w10*b1.w + w01*c1.w + w11*d1.w;
    }
    __syncthreads();

    // ---- phase 2: lane l owns pixel P = 9600*l + q ----
    int l = tid & 7;
    int dbase = tid & ~7;
    int q = (p20 + dbase) >> 3;
    int P = QW * l + q;

    const float4* fvp = (const float4*)(hwc + (size_t)P * 8);
    float4 fa = fvp[0], fb = fvp[1];
    float fv[8] = {fa.x, fa.y, fa.z, fa.w, fb.x, fb.y, fb.z, fb.w};

    float cw[8];
    #pragma unroll
    for (int k = 0; k < 8; k++) {
        float a = 0.0f;
        #pragma unroll
        for (int s = 0; s < 8; s++)
            a = fmaf(fv[s], sS[(dbase + s) * 65 + k * 8 + l], a);
        cw[k] = a;
    }

    const float* oa_b = g_oa + (size_t)b * COUT * HWP;
    const float* gc   = gtconf + (size_t)b * HWP;
    int i = P / WW, j = P - (P / WW) * WW;
    float asc = __ldg(ascp);

    float aff[8];
    float ssum = 0.0f;
    #pragma unroll
    for (int k = 0; k < 8; k++) {
        float araw = __ldg(oa_b + (size_t)(16 + k) * HWP + P);
        float2 od = off_b[(size_t)k * HWP + P];          // (dy, dx)
        float conf = bilin0(gc, od.y + (float)j, od.x + (float)i, HH, WW);
        float a = __fdividef(tanh_fast(araw * cw[k]), asc + 1e-8f) * conf;
        aff[k] = a;
        ssum += fabsf(a);
    }
    float denom = fmaxf(ssum + 1e-4f, 1.0f);
    float tsum = 0.0f;
    #pragma unroll
    for (int k = 0; k < 8; k++) {
        aff[k] = __fdividef(aff[k], denom);
        tsum += aff[k];
    }
    float ref = 1.0f - tsum;
    float mx = ref;
    #pragma unroll
    for (int k = 0; k < 8; k++) mx = fmaxf(mx, aff[k]);
    float er = __expf(ref - mx);
    float se = er;
    float e[8];
    #pragma unroll
    for (int k = 0; k < 8; k++) { e[k] = __expf(aff[k] - mx); se += e[k]; }
    float inv = __fdividef(1.0f, se);

    float* outa = out + (size_t)BB * 18 * HWP + (size_t)b * 9 * HWP;
    #pragma unroll
    for (int k = 0; k < 8; k++) {
        int oc = (k < 4) ? k : k + 1;
        outa[(size_t)oc * HWP + P] = e[k] * inv;
    }
    outa[(size_t)4 * HWP + P] = er * inv;
}

// ============================================================================
extern "C" void kernel_launch(void* const* d_in, const int* in_sizes, int n_in,
                              void* d_out, int out_size) {
    const float* guidance = (const float*)d_in[0];
    const float* gtconf   = (const float*)d_in[1];
    const float* tgt      = (const float*)d_in[2];
    const float* convw    = (const float*)d_in[3];
    const float* convb    = (const float*)d_in[4];
    const float* asc      = (const float*)d_in[5];
    float* out = (float*)d_out;

    cudaFuncSetAttribute(conv_wino_kernel,
                         cudaFuncAttributeMaxDynamicSharedMemorySize, WINO_SMEM);
    cudaFuncSetAttribute(fused_kernel,
                         cudaFuncAttributeMaxDynamicSharedMemorySize, FUSED_SMEM);

    upsample_kernel<<<(BB * HWP + 255) / 256, 256>>>(tgt, out);
    wino_weights_kernel<<<(CIN * COUT + 255) / 256, 256>>>(convw);
    conv_wino_kernel<<<dim3(WW / 16, HH / 8, BB), 256, WINO_SMEM>>>(guidance, convb, out);
    fused_kernel<<<(BB * HWP) / 256, 256, FUSED_SMEM>>>(gtconf, asc, out);
}